// round 7
// baseline (speedup 1.0000x reference)
#include <cuda_runtime.h>
#include <math.h>

#define Bsz 32
#define Nf  4096
#define Kv  1024
#define Dm  1024
#define Hh  16
#define MAXF 4096

typedef unsigned long long u64;

// Single static scratch arena — no allocations anywhere. (84 MB)
__device__ float g_scratch[20971520];

// kv-region offset inside wpart (frame: 16 chunks, kv: 4 chunks)
#define WKV_OFF 8388608

// ---- f32x2 packed helpers ---------------------------------------------------
__device__ __forceinline__ void ffma2(u64& d, u64 a, u64 b)
{
    asm("fma.rn.f32x2 %0, %1, %2, %0;" : "+l"(d) : "l"(a), "l"(b));
}
__device__ __forceinline__ u64 dup2(float a)
{
    u64 r; asm("mov.b64 %0, {%1,%1};" : "=l"(r) : "f"(a)); return r;
}
__device__ __forceinline__ float sum2(u64 v)
{
    float lo, hi; asm("mov.b64 {%0,%1}, %2;" : "=f"(lo), "=f"(hi) : "l"(v));
    return lo + hi;
}

// ---------------- mean over frame tokens (split into 16 partials) -------------
__global__ void k_mean_part(const float* __restrict__ frame, float* __restrict__ mpart)
{
    int b = blockIdx.x, sp = blockIdx.y, tid = threadIdx.x;
    const float4* fp = (const float4*)(frame + ((size_t)b * Nf + sp * 256) * Dm) + tid;
    float4 acc = make_float4(0.f, 0.f, 0.f, 0.f);
    #pragma unroll 4
    for (int n = 0; n < 256; n++) {
        float4 v = fp[(size_t)n * 256];
        acc.x += v.x; acc.y += v.y; acc.z += v.z; acc.w += v.w;
    }
    ((float4*)(mpart + ((size_t)sp * Bsz + b) * Dm))[tid] = acc;
}

// ---------------- q init ------------------------------------------------------
__global__ void k_qinit(const float* __restrict__ mpart, const float* __restrict__ mi,
                        const float* __restrict__ qb, const float* __restrict__ role,
                        const float* __restrict__ tw, const int* __restrict__ fidx,
                        float* __restrict__ q)
{
    int b = blockIdx.x, tid = threadIdx.x;
    float4 m = make_float4(0.f, 0.f, 0.f, 0.f);
    for (int sp = 0; sp < 16; sp++) {
        float4 v = ((const float4*)(mpart + ((size_t)sp * Bsz + b) * Dm))[tid];
        m.x += v.x; m.y += v.y; m.z += v.z; m.w += v.w;
    }
    const float inv = 1.f / (float)Nf;
    int t = fidx[b]; t = t < 0 ? 0 : (t > MAXF - 1 ? MAXF - 1 : t);
    float4 te = ((const float4*)(tw + (size_t)t * Dm))[tid];
    float4 q0 = ((const float4*)qb)[tid];
    float4 q1 = ((const float4*)(qb + Dm))[tid];
    float4 r0 = ((const float4*)role)[tid];
    float4 r1 = ((const float4*)(role + Dm))[tid];
    float4 mv = ((const float4*)(mi + (size_t)b * Dm))[tid];
    float4 o0, o1;
    o0.x = m.x * inv + q0.x + r0.x + te.x;  o0.y = m.y * inv + q0.y + r0.y + te.y;
    o0.z = m.z * inv + q0.z + r0.z + te.z;  o0.w = m.w * inv + q0.w + r0.w + te.w;
    o1.x = mv.x + q1.x + r1.x + te.x;       o1.y = mv.y + q1.y + r1.y + te.y;
    o1.z = mv.z + q1.z + r1.z + te.z;       o1.w = mv.w + q1.w + r1.w + te.w;
    ((float4*)(q + (size_t)b * 2 * Dm))[tid] = o0;
    ((float4*)(q + (size_t)b * 2 * Dm + Dm))[tid] = o1;
}

// ---------------- LayerNorm (standalone; only used once at init) -------------
__global__ void k_ln(const float* __restrict__ in, const float* __restrict__ g,
                     const float* __restrict__ b, float* __restrict__ outp)
{
    __shared__ float2 red[256];
    int row = blockIdx.x, tid = threadIdx.x;
    float4 v = ((const float4*)(in + (size_t)row * Dm))[tid];
    float s = v.x + v.y + v.z + v.w;
    float sq = v.x * v.x + v.y * v.y + v.z * v.z + v.w * v.w;
    red[tid] = make_float2(s, sq); __syncthreads();
    for (int st = 128; st > 0; st >>= 1) {
        if (tid < st) { red[tid].x += red[tid + st].x; red[tid].y += red[tid + st].y; }
        __syncthreads();
    }
    float mean = red[0].x * (1.f / 1024.f);
    float var  = red[0].y * (1.f / 1024.f) - mean * mean;
    float rstd = rsqrtf(var + 1e-5f);
    float4 gv = ((const float4*)g)[tid];
    float4 bv = ((const float4*)b)[tid];
    float4 o;
    o.x = (v.x - mean) * rstd * gv.x + bv.x;
    o.y = (v.y - mean) * rstd * gv.y + bv.y;
    o.z = (v.z - mean) * rstd * gv.z + bv.z;
    o.w = (v.w - mean) * rstd * gv.w + bv.w;
    ((float4*)(outp + (size_t)row * Dm))[tid] = o;
}

// ---------------- small GEMM (R3-measured-best schedule + pairing) -----------
// part[ks][mbase+m][n] = Ab[m, kchunk] @ Wb[n0+n, kchunk]^T
// grid: (N/64, npair, splitK). blockIdx.y selects (A,W) member; mbase = y*M.
__global__ __launch_bounds__(256) void k_gemm_part(
    const float* __restrict__ A, const float* __restrict__ A2, int lda, int M,
    const float* __restrict__ W, const float* __restrict__ W2, int K,
    float* __restrict__ part, int N, int kchunk, int Mtot)
{
    __shared__ float As[16][64];
    __shared__ float Ws[16][64];
    int tid = threadIdx.x;
    int n0 = blockIdx.x * 64;
    int pm = blockIdx.y;
    int ks = blockIdx.z;
    const float* Ab = pm ? A2 : A;
    const float* Wb = pm ? W2 : W;
    int mbase = pm * M;
    int ty = tid >> 4, tx = tid & 15;
    int lm = tid >> 2;
    int lk = (tid & 3) << 2;
    u64 acc[4][2];
    #pragma unroll
    for (int i = 0; i < 4; i++) { acc[i][0] = 0ULL; acc[i][1] = 0ULL; }

    const float* Ap = Ab + (size_t)lm * lda;
    const float* Wp = Wb + (size_t)(n0 + lm) * K;
    int kend = ks * kchunk + kchunk;
    for (int kk = ks * kchunk; kk < kend; kk += 16) {
        float4 av = make_float4(0.f, 0.f, 0.f, 0.f);
        if (lm < M) av = *(const float4*)(Ap + kk + lk);
        float4 wv = *(const float4*)(Wp + kk + lk);
        __syncthreads();
        As[lk + 0][lm] = av.x; As[lk + 1][lm] = av.y; As[lk + 2][lm] = av.z; As[lk + 3][lm] = av.w;
        Ws[lk + 0][lm] = wv.x; Ws[lk + 1][lm] = wv.y; Ws[lk + 2][lm] = wv.z; Ws[lk + 3][lm] = wv.w;
        __syncthreads();
        #pragma unroll
        for (int k2 = 0; k2 < 16; k2++) {
            float4 a = *(const float4*)&As[k2][ty << 2];
            ulonglong2 w = *(const ulonglong2*)&Ws[k2][tx << 2];
            u64 d0 = dup2(a.x), d1 = dup2(a.y), d2 = dup2(a.z), d3 = dup2(a.w);
            ffma2(acc[0][0], d0, w.x); ffma2(acc[0][1], d0, w.y);
            ffma2(acc[1][0], d1, w.x); ffma2(acc[1][1], d1, w.y);
            ffma2(acc[2][0], d2, w.x); ffma2(acc[2][1], d2, w.y);
            ffma2(acc[3][0], d3, w.x); ffma2(acc[3][1], d3, w.y);
        }
    }
    float* P = part + ((size_t)ks * Mtot + mbase) * N;
    #pragma unroll
    for (int i = 0; i < 4; i++) {
        int m = (ty << 2) + i;
        if (m < M) {
            ulonglong2 v; v.x = acc[i][0]; v.y = acc[i][1];
            *(ulonglong2*)(P + (size_t)m * N + n0 + (tx << 2)) = v;
        }
    }
}

__device__ __forceinline__ float gelu_exact(float x)
{
    return 0.5f * x * (1.f + erff(x * 0.70710678118654752f));
}

// generic reduce (no LN): sa_in, ffn1
__global__ void k_gemm_reduce(const float* __restrict__ part,
                              float* __restrict__ C, int ldc,
                              const float* __restrict__ bias,
                              int M, int N, int nsplit, int act)
{
    int n = blockIdx.x * 256 + threadIdx.x;
    int m = blockIdx.y;
    if (n >= N) return;
    float s = 0.f;
    for (int ks = 0; ks < nsplit; ks++) s += part[((size_t)ks * M + m) * N + n];
    s += bias[n];
    if (act) s = gelu_exact(s);
    C[(size_t)m * ldc + n] = s;
}

// paired reduce (qproj): part M=64 (g rows 0-31, s rows 32-63), N=1024
__global__ void k_reduce_pair(const float* __restrict__ part, int nsplit,
                              const float* __restrict__ bA, const float* __restrict__ bB,
                              float* __restrict__ CA, float* __restrict__ CB)
{
    int n = blockIdx.x * 256 + threadIdx.x;
    int m = blockIdx.y;
    float s = 0.f;
    for (int ks = 0; ks < nsplit; ks++) s += part[((size_t)ks * 64 + m) * 1024 + n];
    if (m < 32) CA[(size_t)m * 1024 + n] = s + bA[n];
    else        CB[(size_t)(m - 32) * 1024 + n] = s + bB[n];
}

// reduce + bias + residual -> C(row), then LayerNorm -> X(row). N==1024.
__global__ void k_reduce_ln(const float* __restrict__ part, int M, int nsplit,
                            const float* __restrict__ bias,
                            float* __restrict__ C, int ldc,
                            const float* __restrict__ lng, const float* __restrict__ lnb,
                            float* __restrict__ X, int ldx)
{
    __shared__ float2 red[256];
    int m = blockIdx.x, tid = threadIdx.x;
    float4 s4 = make_float4(0.f, 0.f, 0.f, 0.f);
    for (int ks = 0; ks < nsplit; ks++) {
        float4 v = ((const float4*)(part + ((size_t)ks * M + m) * 1024))[tid];
        s4.x += v.x; s4.y += v.y; s4.z += v.z; s4.w += v.w;
    }
    float4 bb = ((const float4*)bias)[tid];
    float4 rr = ((const float4*)(C + (size_t)m * ldc))[tid];
    s4.x += bb.x + rr.x; s4.y += bb.y + rr.y;
    s4.z += bb.z + rr.z; s4.w += bb.w + rr.w;
    ((float4*)(C + (size_t)m * ldc))[tid] = s4;
    float s = s4.x + s4.y + s4.z + s4.w;
    float sq = s4.x * s4.x + s4.y * s4.y + s4.z * s4.z + s4.w * s4.w;
    red[tid] = make_float2(s, sq); __syncthreads();
    for (int st = 128; st > 0; st >>= 1) {
        if (tid < st) { red[tid].x += red[tid + st].x; red[tid].y += red[tid + st].y; }
        __syncthreads();
    }
    float mean = red[0].x * (1.f / 1024.f);
    float var  = red[0].y * (1.f / 1024.f) - mean * mean;
    float rstd = rsqrtf(var + 1e-5f);
    float4 gv = ((const float4*)lng)[tid];
    float4 bv = ((const float4*)lnb)[tid];
    float4 o;
    o.x = (s4.x - mean) * rstd * gv.x + bv.x;
    o.y = (s4.y - mean) * rstd * gv.y + bv.y;
    o.z = (s4.z - mean) * rstd * gv.z + bv.z;
    o.w = (s4.w - mean) * rstd * gv.w + bv.w;
    ((float4*)(X + (size_t)m * ldx))[tid] = o;
}

// paired reduce+res+LN for out-projections (g rows 0-31, s rows 32-63 in part)
__global__ void k_reduce_ln_pair(const float* __restrict__ part, int nsplit,
                                 const float* __restrict__ bA, const float* __restrict__ bB,
                                 float* __restrict__ q,
                                 const float* __restrict__ lng, const float* __restrict__ lnb,
                                 float* __restrict__ x)
{
    __shared__ float2 red[256];
    int m = blockIdx.x, tid = threadIdx.x;
    float* qrow; const float* bias; float* xrow;
    if (m < 32) { qrow = q + (size_t)m * 2048; bias = bA; xrow = x + (size_t)m * 2048; }
    else { qrow = q + (size_t)(m - 32) * 2048 + 1024; bias = bB; xrow = x + (size_t)(m - 32) * 2048 + 1024; }
    float4 s4 = make_float4(0.f, 0.f, 0.f, 0.f);
    for (int ks = 0; ks < nsplit; ks++) {
        float4 v = ((const float4*)(part + ((size_t)ks * 64 + m) * 1024))[tid];
        s4.x += v.x; s4.y += v.y; s4.z += v.z; s4.w += v.w;
    }
    float4 bb = ((const float4*)bias)[tid];
    float4 rr = ((const float4*)qrow)[tid];
    s4.x += bb.x + rr.x; s4.y += bb.y + rr.y;
    s4.z += bb.z + rr.z; s4.w += bb.w + rr.w;
    ((float4*)qrow)[tid] = s4;
    float s = s4.x + s4.y + s4.z + s4.w;
    float sq = s4.x * s4.x + s4.y * s4.y + s4.z * s4.z + s4.w * s4.w;
    red[tid] = make_float2(s, sq); __syncthreads();
    for (int st = 128; st > 0; st >>= 1) {
        if (tid < st) { red[tid].x += red[tid + st].x; red[tid].y += red[tid + st].y; }
        __syncthreads();
    }
    float mean = red[0].x * (1.f / 1024.f);
    float var  = red[0].y * (1.f / 1024.f) - mean * mean;
    float rstd = rsqrtf(var + 1e-5f);
    float4 gv = ((const float4*)lng)[tid];
    float4 bv = ((const float4*)lnb)[tid];
    float4 o;
    o.x = (s4.x - mean) * rstd * gv.x + bv.x;
    o.y = (s4.y - mean) * rstd * gv.y + bv.y;
    o.z = (s4.z - mean) * rstd * gv.z + bv.z;
    o.w = (s4.w - mean) * rstd * gv.w + bv.w;
    ((float4*)xrow)[tid] = o;
}

// ---------------- 2-token self-attention core --------------------------------
__global__ void k_selfattn(const float* __restrict__ t3, float* __restrict__ attn)
{
    int b = blockIdx.x, h = blockIdx.y, d = threadIdx.x;
    const float* r0 = t3 + (size_t)(b * 2 + 0) * 3072;
    const float* r1 = t3 + (size_t)(b * 2 + 1) * 3072;
    int j = h * 64 + d;
    float q0 = r0[j], k0 = r0[1024 + j], v0 = r0[2048 + j];
    float q1 = r1[j], k1 = r1[1024 + j], v1 = r1[2048 + j];
    __shared__ float sh[4][64];
    sh[0][d] = q0 * k0; sh[1][d] = q0 * k1; sh[2][d] = q1 * k0; sh[3][d] = q1 * k1;
    __syncthreads();
    for (int st = 32; st > 0; st >>= 1) {
        if (d < st) {
            #pragma unroll
            for (int i = 0; i < 4; i++) sh[i][d] += sh[i][d + st];
        }
        __syncthreads();
    }
    float s00 = sh[0][0] * 0.125f, s01 = sh[1][0] * 0.125f;
    float s10 = sh[2][0] * 0.125f, s11 = sh[3][0] * 0.125f;
    float m0 = fmaxf(s00, s01), m1 = fmaxf(s10, s11);
    float e00 = expf(s00 - m0), e01 = expf(s01 - m0);
    float e10 = expf(s10 - m1), e11 = expf(s11 - m1);
    float a00 = e00 / (e00 + e01), a01 = e01 / (e00 + e01);
    float a10 = e10 / (e10 + e11), a11 = e11 / (e10 + e11);
    attn[(size_t)(b * 2 + 0) * Dm + j] = a00 * v0 + a01 * v1;
    attn[(size_t)(b * 2 + 1) * Dm + j] = a10 * v0 + a11 * v1;
}

// ---------------- fold (merged g/s): u[b,h,:] = qp[b, h*64: ] @ wk_h ---------
__global__ void k_ufold(const float* __restrict__ qpg, const float* __restrict__ qps,
                        const float* __restrict__ wkg, const float* __restrict__ wks,
                        float* __restrict__ ug, float* __restrict__ us)
{
    const float* qp = blockIdx.z ? qps : qpg;
    const float* wk = blockIdx.z ? wks : wkg;
    float* u = blockIdx.z ? us : ug;
    int h = blockIdx.x;
    int e = blockIdx.y * 128 + threadIdx.x;
    __shared__ float qs[32][64];
    for (int i = threadIdx.x; i < 2048; i += 128)
        qs[i >> 6][i & 63] = qp[(size_t)(i >> 6) * Dm + h * 64 + (i & 63)];
    __syncthreads();
    float acc[32];
    #pragma unroll
    for (int b2 = 0; b2 < 32; b2++) acc[b2] = 0.f;
    for (int d = 0; d < 64; d++) {
        float w = wk[(size_t)(h * 64 + d) * Dm + e];
        #pragma unroll
        for (int b2 = 0; b2 < 32; b2++) acc[b2] += qs[b2][d] * w;
    }
    #pragma unroll
    for (int b2 = 0; b2 < 32; b2++) u[((size_t)b2 * Hh + h) * Dm + e] = acc[b2];
}

// ---------------- scores (merged frame/kv, 8 heads x 4 tokens per warp) ------
// block: 256 thr = 8 warps; warp = (head-half, token-quad); 32 tokens/block.
__global__ __launch_bounds__(256) void k_scores(
    const float* __restrict__ frame, const float* __restrict__ kvs,
    const float* __restrict__ ug, const float* __restrict__ us,
    float* __restrict__ sg, float* __restrict__ ss)
{
    extern __shared__ float ush[];   // 64 KB: all 16 heads of u
    int b = blockIdx.x, by = blockIdx.y, tid = threadIdx.x;
    const float* X; const float* u; float* s; int Nt, tile;
    if (by < 128) { X = frame; u = ug; s = sg; Nt = Nf; tile = by; }
    else          { X = kvs;   u = us; s = ss; Nt = Kv; tile = by - 128; }
    const float4* usrc = (const float4*)(u + (size_t)b * Hh * Dm);
    #pragma unroll
    for (int i = 0; i < 16; i++) ((float4*)ush)[tid + i * 256] = usrc[tid + i * 256];
    __syncthreads();
    int w = tid >> 5, lane = tid & 31;
    int hh = (w & 1) << 3;    // head base: 0 or 8
    int tq = w >> 1;          // token quad: 0..3
    #pragma unroll
    for (int tl = 0; tl < 2; tl++) {
        int n0 = tile * 32 + tl * 16 + tq * 4;
        const ulonglong2* xp = (const ulonglong2*)(X + ((size_t)b * Nt + n0) * Dm);
        u64 acc[8][4];
        #pragma unroll
        for (int h = 0; h < 8; h++)
            #pragma unroll
            for (int t = 0; t < 4; t++) acc[h][t] = 0ULL;
        #pragma unroll
        for (int i = 0; i < 8; i++) {
            ulonglong2 x0 = xp[0 * 256 + i * 32 + lane];
            ulonglong2 x1 = xp[1 * 256 + i * 32 + lane];
            ulonglong2 x2 = xp[2 * 256 + i * 32 + lane];
            ulonglong2 x3 = xp[3 * 256 + i * 32 + lane];
            #pragma unroll
            for (int h = 0; h < 8; h++) {
                ulonglong2 uv = *(const ulonglong2*)&ush[(hh + h) * Dm + i * 128 + (lane << 2)];
                ffma2(acc[h][0], x0.x, uv.x); ffma2(acc[h][0], x0.y, uv.y);
                ffma2(acc[h][1], x1.x, uv.x); ffma2(acc[h][1], x1.y, uv.y);
                ffma2(acc[h][2], x2.x, uv.x); ffma2(acc[h][2], x2.y, uv.y);
                ffma2(acc[h][3], x3.x, uv.x); ffma2(acc[h][3], x3.y, uv.y);
            }
        }
        #pragma unroll
        for (int h = 0; h < 8; h++) {
            #pragma unroll
            for (int t = 0; t < 4; t++) {
                float v = sum2(acc[h][t]);
                #pragma unroll
                for (int off = 16; off; off >>= 1) v += __shfl_xor_sync(0xffffffffu, v, off);
                if (lane == 0) s[((size_t)b * Hh + hh + h) * Nt + n0 + t] = v * 0.125f;
            }
        }
    }
}

// ---------------- softmax (merged frame/kv) ----------------------------------
template <int CNT>
__device__ __forceinline__ void softmax_row(float* __restrict__ s, float* red)
{
    int tid = threadIdx.x;
    float v[CNT];
    float mx = -1e30f;
    #pragma unroll
    for (int i = 0; i < CNT; i++) { v[i] = s[i * 256 + tid]; mx = fmaxf(mx, v[i]); }
    red[tid] = mx; __syncthreads();
    for (int st = 128; st > 0; st >>= 1) {
        if (tid < st) red[tid] = fmaxf(red[tid], red[tid + st]);
        __syncthreads();
    }
    mx = red[0]; __syncthreads();
    float sum = 0.f;
    #pragma unroll
    for (int i = 0; i < CNT; i++) { v[i] = expf(v[i] - mx); sum += v[i]; }
    red[tid] = sum; __syncthreads();
    for (int st = 128; st > 0; st >>= 1) {
        if (tid < st) red[tid] += red[tid + st];
        __syncthreads();
    }
    float inv = 1.f / red[0];
    #pragma unroll
    for (int i = 0; i < CNT; i++) s[i * 256 + tid] = v[i] * inv;
}

__global__ void k_softmax2(float* __restrict__ sg, float* __restrict__ ss)
{
    __shared__ float red[256];
    int id = blockIdx.x;
    if (id < 512) softmax_row<16>(sg + (size_t)id * Nf, red);
    else          softmax_row<4>(ss + (size_t)(id - 512) * Kv, red);
}

// ---------------- wbar partials (merged frame/kv, broadcast LDS.128) ---------
__global__ __launch_bounds__(256) void k_wbar(
    const float* __restrict__ frame, const float* __restrict__ kvs,
    const float* __restrict__ sg, const float* __restrict__ ss,
    float* __restrict__ wpart)
{
    __shared__ __align__(16) u64 ash[16][258];
    int b = blockIdx.x, sp = blockIdx.y, tid = threadIdx.x;
    const float* X; const float* a; int Nt, n0; float* dst;
    if (sp < 16) {
        X = frame; a = sg; Nt = Nf; n0 = sp * 256;
        dst = wpart + ((size_t)sp * Bsz + b) * (Hh * Dm);
    } else {
        int k2 = sp - 16;
        X = kvs; a = ss; Nt = Kv; n0 = k2 * 256;
        dst = wpart + WKV_OFF + ((size_t)k2 * Bsz + b) * (Hh * Dm);
    }
    for (int idx = tid; idx < 4096; idx += 256) {
        int nn = idx & 255, h = idx >> 8;
        ash[h][nn] = dup2(a[((size_t)b * Hh + h) * Nt + n0 + nn]);
    }
    __syncthreads();
    u64 acc[16][2];
    #pragma unroll
    for (int h = 0; h < 16; h++) { acc[h][0] = 0ULL; acc[h][1] = 0ULL; }
    const ulonglong2* xp = (const ulonglong2*)(X + ((size_t)b * Nt + n0) * Dm) + tid;
    for (int nn = 0; nn < 256; nn += 2) {
        ulonglong2 f0 = xp[(size_t)nn * 256];
        ulonglong2 f1 = xp[(size_t)(nn + 1) * 256];
        #pragma unroll
        for (int h = 0; h < 16; h++) {
            ulonglong2 ap = *(const ulonglong2*)&ash[h][nn];
            ffma2(acc[h][0], ap.x, f0.x);
            ffma2(acc[h][1], ap.x, f0.y);
            ffma2(acc[h][0], ap.y, f1.x);
            ffma2(acc[h][1], ap.y, f1.y);
        }
    }
    ulonglong2* P = (ulonglong2*)dst;
    #pragma unroll
    for (int h = 0; h < 16; h++) {
        ulonglong2 v; v.x = acc[h][0]; v.y = acc[h][1];
        P[h * 256 + tid] = v;
    }
}

// ---------------- v-projection (merged g/s, fused split reduce) --------------
__global__ void k_vproj(const float* __restrict__ wpart,
                        const float* __restrict__ wvg, const float* __restrict__ bvg,
                        const float* __restrict__ wvs, const float* __restrict__ bvs,
                        float* __restrict__ og, float* __restrict__ os)
{
    __shared__ float wsh[1024];
    int b = blockIdx.x, y = blockIdx.y, tid = threadIdx.x;
    int h, NS; const float* base; const float* wv; const float* bv; float* o;
    if (y < 16) { h = y;      NS = 16; base = wpart;           wv = wvg; bv = bvg; o = og; }
    else        { h = y - 16; NS = 4;  base = wpart + WKV_OFF; wv = wvs; bv = bvs; o = os; }
    float4 acc4 = make_float4(0.f, 0.f, 0.f, 0.f);
    for (int sp = 0; sp < NS; sp++) {
        float4 v = ((const float4*)(base + (((size_t)sp * Bsz + b) * Hh + h) * Dm))[tid];
        acc4.x += v.x; acc4.y += v.y; acc4.z += v.z; acc4.w += v.w;
    }
    ((float4*)wsh)[tid] = acc4;
    __syncthreads();
    int w = tid >> 5, lane = tid & 31;
    for (int dd = w; dd < 64; dd += 8) {
        int j = h * 64 + dd;
        const float4* wvp = (const float4*)(wv + (size_t)j * Dm);
        float acc = 0.f;
        #pragma unroll
        for (int i = 0; i < 8; i++) {
            float4 a = wvp[i * 32 + lane];
            float4 c = *(const float4*)&wsh[i * 128 + (lane << 2)];
            acc += a.x * c.x + a.y * c.y + a.z * c.z + a.w * c.w;
        }
        #pragma unroll
        for (int off = 16; off; off >>= 1) acc += __shfl_xor_sync(0xffffffffu, acc, off);
        if (lane == 0) o[(size_t)b * Dm + j] = acc + bv[j];
    }
}

extern "C" void kernel_launch(void* const* d_in, const int* in_sizes, int n_in,
                              void* d_out, int out_size)
{
    const float* frame = (const float*)d_in[0];
    const float* kvs   = (const float*)d_in[1];
    const float* maxi  = (const float*)d_in[2];
    const float* qbase = (const float*)d_in[3];
    const float* role  = (const float*)d_in[4];
    const float* timew = (const float*)d_in[5];
    const float* ln1g  = (const float*)d_in[6];
    const float* ln1b  = (const float*)d_in[7];
    const float* sa_in_w = (const float*)d_in[8];
    const float* sa_in_b = (const float*)d_in[9];
    const float* sa_out_w = (const float*)d_in[10];
    const float* sa_out_b = (const float*)d_in[11];
    const float* ln2g  = (const float*)d_in[12];
    const float* ln2b  = (const float*)d_in[13];
    const float* cg_in_w = (const float*)d_in[14];
    const float* cg_in_b = (const float*)d_in[15];
    const float* cg_out_w = (const float*)d_in[16];
    const float* cg_out_b = (const float*)d_in[17];
    const float* cs_in_w = (const float*)d_in[18];
    const float* cs_in_b = (const float*)d_in[19];
    const float* cs_out_w = (const float*)d_in[20];
    const float* cs_out_b = (const float*)d_in[21];
    const float* ln3g  = (const float*)d_in[22];
    const float* ln3b  = (const float*)d_in[23];
    const float* fw1   = (const float*)d_in[24];
    const float* fb1   = (const float*)d_in[25];
    const float* fw2   = (const float*)d_in[26];
    const float* fb2   = (const float*)d_in[27];
    const float* outg  = (const float*)d_in[28];
    const float* outb  = (const float*)d_in[29];
    const int*   fidx  = (const int*)d_in[30];
    float* outp = (float*)d_out;

    void* sp_;
    cudaGetSymbolAddress(&sp_, g_scratch);
    float* S = (float*)sp_;
    float* mpart = S;                   // 524288
    float* q     = mpart + 524288;      // 65536
    float* x     = q + 65536;           // 65536
    float* t3    = x + 65536;           // 196608
    float* attn  = t3 + 196608;         // 65536
    float* qpg   = attn + 65536;        // 32768
    float* qps   = qpg + 32768;         // 32768
    float* ug    = qps + 32768;         // 524288
    float* us    = ug + 524288;         // 524288
    float* sg    = us + 524288;         // 2097152
    float* ss    = sg + 2097152;        // 524288
    float* wpart = ss + 524288;         // 10485760 (frame 16 + kv 4 chunks)
    float* og    = wpart + 10485760;    // 32768
    float* os    = og + 32768;          // 32768
    float* gpart = os + 32768;          // 3145728
    float* hh    = gpart + 3145728;     // 262144

    cudaFuncSetAttribute(k_scores, cudaFuncAttributeMaxDynamicSharedMemorySize, 65536);

    // init: mean + q assembly + first LN
    k_mean_part<<<dim3(32, 16), 256>>>(frame, mpart);
    k_qinit<<<32, 256>>>(mpart, maxi, qbase, role, timew, fidx, q);
    k_ln<<<64, 256>>>(q, ln1g, ln1b, x);

    for (int l = 0; l < 2; l++) {
        const float* siw = sa_in_w + (size_t)l * 3072 * Dm;
        const float* sib = sa_in_b + l * 3072;
        const float* sow = sa_out_w + (size_t)l * Dm * Dm;
        const float* sob = sa_out_b + l * Dm;
        const float* l2g = ln2g + l * Dm;   const float* l2b = ln2b + l * Dm;
        const float* giw = cg_in_w + (size_t)l * 3072 * Dm;
        const float* gib = cg_in_b + l * 3072;
        const float* gow = cg_out_w + (size_t)l * Dm * Dm;
        const float* gob = cg_out_b + l * Dm;
        const float* ciw = cs_in_w + (size_t)l * 3072 * Dm;
        const float* cib = cs_in_b + l * 3072;
        const float* cow = cs_out_w + (size_t)l * Dm * Dm;
        const float* cob = cs_out_b + l * Dm;
        const float* l3g = ln3g + l * Dm;   const float* l3b = ln3b + l * Dm;
        const float* w1 = fw1 + (size_t)l * 4096 * Dm;
        const float* b1 = fb1 + l * 4096;
        const float* w2 = fw2 + (size_t)l * Dm * 4096;
        const float* b2 = fb2 + l * Dm;
        const float* nlg = (l == 0) ? (ln1g + Dm) : outg;
        const float* nlb = (l == 0) ? (ln1b + Dm) : outb;
        float* nx = (l == 0) ? x : outp;

        // ---- self-attention (2 tokens): x is LN1(q) ----
        k_gemm_part<<<dim3(48, 1, 16), 256>>>(x, nullptr, 1024, 64, siw, nullptr, 1024,
                                              gpart, 3072, 64, 64);
        k_gemm_reduce<<<dim3(12, 64), 256>>>(gpart, t3, 3072, sib, 64, 3072, 16, 0);
        k_selfattn<<<dim3(32, 16), 64>>>(t3, attn);
        k_gemm_part<<<dim3(16, 1, 16), 256>>>(attn, nullptr, 1024, 64, sow, nullptr, 1024,
                                              gpart, 1024, 64, 64);
        k_reduce_ln<<<64, 256>>>(gpart, 64, 16, sob, q, 1024, l2g, l2b, x, 1024);

        // ---- cross-attention (folded K/V), g+s paired ----
        k_gemm_part<<<dim3(16, 2, 16), 256>>>(x, x + 1024, 2048, 32, giw, ciw, 1024,
                                              gpart, 1024, 64, 64);
        k_reduce_pair<<<dim3(4, 64), 256>>>(gpart, 16, gib, cib, qpg, qps);
        k_ufold<<<dim3(16, 8, 2), 128>>>(qpg, qps, giw + 1024 * 1024, ciw + 1024 * 1024, ug, us);
        k_scores<<<dim3(32, 160), 256, 65536>>>(frame, kvs, ug, us, sg, ss);
        k_softmax2<<<1024, 256>>>(sg, ss);
        k_wbar<<<dim3(32, 20), 256>>>(frame, kvs, sg, ss, wpart);
        k_vproj<<<dim3(32, 32), 256>>>(wpart, giw + 2 * 1024 * 1024, gib + 2048,
                                       ciw + 2 * 1024 * 1024, cib + 2048, og, os);
        k_gemm_part<<<dim3(16, 2, 16), 256>>>(og, os, 1024, 32, gow, cow, 1024,
                                              gpart, 1024, 64, 64);
        k_reduce_ln_pair<<<64, 256>>>(gpart, 16, gob, cob, q, l3g, l3b, x);

        // ---- FFN: x is LN3(q) ----
        k_gemm_part<<<dim3(64, 1, 8), 256>>>(x, nullptr, 1024, 64, w1, nullptr, 1024,
                                             gpart, 4096, 128, 64);
        k_gemm_reduce<<<dim3(16, 64), 256>>>(gpart, hh, 4096, b1, 64, 4096, 8, 1);
        k_gemm_part<<<dim3(16, 1, 32), 256>>>(hh, nullptr, 4096, 64, w2, nullptr, 4096,
                                              gpart, 1024, 128, 64);
        k_reduce_ln<<<64, 256>>>(gpart, 64, 32, b2, q, 1024, nlg, nlb, nx, 1024);
    }
}

// round 8
// speedup vs baseline: 1.2241x; 1.2241x over previous
#include <cuda_runtime.h>
#include <math.h>

#define Bsz 32
#define Nf  4096
#define Kv  1024
#define Dm  1024
#define Hh  16
#define MAXF 4096

typedef unsigned long long u64;

// Single static scratch arena — no allocations anywhere.
__device__ float g_scratch[16777216];

// ---- f32x2 packed helpers ---------------------------------------------------
__device__ __forceinline__ void ffma2(u64& d, u64 a, u64 b)
{
    asm("fma.rn.f32x2 %0, %1, %2, %0;" : "+l"(d) : "l"(a), "l"(b));
}
__device__ __forceinline__ u64 dup2(float a)
{
    u64 r; asm("mov.b64 %0, {%1,%1};" : "=l"(r) : "f"(a)); return r;
}
__device__ __forceinline__ float sum2(u64 v)
{
    float lo, hi; asm("mov.b64 {%0,%1}, %2;" : "=f"(lo), "=f"(hi) : "l"(v));
    return lo + hi;
}
__device__ __forceinline__ void unpack2(u64 v, float& lo, float& hi)
{
    asm("mov.b64 {%0,%1}, %2;" : "=f"(lo), "=f"(hi) : "l"(v));
}
__device__ __forceinline__ float f4c(const float4& v, int c)
{
    return c == 0 ? v.x : c == 1 ? v.y : c == 2 ? v.z : v.w;
}

// ---------------- mean over frame tokens (split into 16 partials) -------------
__global__ void k_mean_part(const float* __restrict__ frame, float* __restrict__ mpart)
{
    int b = blockIdx.x, sp = blockIdx.y, tid = threadIdx.x;
    const float4* fp = (const float4*)(frame + ((size_t)b * Nf + sp * 256) * Dm) + tid;
    float4 acc = make_float4(0.f, 0.f, 0.f, 0.f);
    #pragma unroll 4
    for (int n = 0; n < 256; n++) {
        float4 v = fp[(size_t)n * 256];
        acc.x += v.x; acc.y += v.y; acc.z += v.z; acc.w += v.w;
    }
    ((float4*)(mpart + ((size_t)sp * Bsz + b) * Dm))[tid] = acc;
}

// ---------------- q init ------------------------------------------------------
__global__ void k_qinit(const float* __restrict__ mpart, const float* __restrict__ mi,
                        const float* __restrict__ qb, const float* __restrict__ role,
                        const float* __restrict__ tw, const int* __restrict__ fidx,
                        float* __restrict__ q)
{
    int b = blockIdx.x, tid = threadIdx.x;
    float4 m = make_float4(0.f, 0.f, 0.f, 0.f);
    for (int sp = 0; sp < 16; sp++) {
        float4 v = ((const float4*)(mpart + ((size_t)sp * Bsz + b) * Dm))[tid];
        m.x += v.x; m.y += v.y; m.z += v.z; m.w += v.w;
    }
    const float inv = 1.f / (float)Nf;
    int t = fidx[b]; t = t < 0 ? 0 : (t > MAXF - 1 ? MAXF - 1 : t);
    float4 te = ((const float4*)(tw + (size_t)t * Dm))[tid];
    float4 q0 = ((const float4*)qb)[tid];
    float4 q1 = ((const float4*)(qb + Dm))[tid];
    float4 r0 = ((const float4*)role)[tid];
    float4 r1 = ((const float4*)(role + Dm))[tid];
    float4 mv = ((const float4*)(mi + (size_t)b * Dm))[tid];
    float4 o0, o1;
    o0.x = m.x * inv + q0.x + r0.x + te.x;  o0.y = m.y * inv + q0.y + r0.y + te.y;
    o0.z = m.z * inv + q0.z + r0.z + te.z;  o0.w = m.w * inv + q0.w + r0.w + te.w;
    o1.x = mv.x + q1.x + r1.x + te.x;       o1.y = mv.y + q1.y + r1.y + te.y;
    o1.z = mv.z + q1.z + r1.z + te.z;       o1.w = mv.w + q1.w + r1.w + te.w;
    ((float4*)(q + (size_t)b * 2 * Dm))[tid] = o0;
    ((float4*)(q + (size_t)b * 2 * Dm + Dm))[tid] = o1;
}

// ---------------- LayerNorm (standalone; init only) --------------------------
__global__ void k_ln(const float* __restrict__ in, const float* __restrict__ g,
                     const float* __restrict__ b, float* __restrict__ outp)
{
    __shared__ float2 red[256];
    int row = blockIdx.x, tid = threadIdx.x;
    float4 v = ((const float4*)(in + (size_t)row * Dm))[tid];
    float s = v.x + v.y + v.z + v.w;
    float sq = v.x * v.x + v.y * v.y + v.z * v.z + v.w * v.w;
    red[tid] = make_float2(s, sq); __syncthreads();
    for (int st = 128; st > 0; st >>= 1) {
        if (tid < st) { red[tid].x += red[tid + st].x; red[tid].y += red[tid + st].y; }
        __syncthreads();
    }
    float mean = red[0].x * (1.f / 1024.f);
    float var  = red[0].y * (1.f / 1024.f) - mean * mean;
    float rstd = rsqrtf(var + 1e-5f);
    float4 gv = ((const float4*)g)[tid];
    float4 bv = ((const float4*)b)[tid];
    float4 o;
    o.x = (v.x - mean) * rstd * gv.x + bv.x;
    o.y = (v.y - mean) * rstd * gv.y + bv.y;
    o.z = (v.z - mean) * rstd * gv.z + bv.z;
    o.w = (v.w - mean) * rstd * gv.w + bv.w;
    ((float4*)(outp + (size_t)row * Dm))[tid] = o;
}

// ---------------- W-register-streaming GEMM ----------------------------------
// part[ks][m][n] = A[m, kchunk] @ W[n0+n, kchunk]^T ; tile MT x 128.
// Thread: 4 W rows (n = n0+tx*4..+3) streamed via registers; MT/8 m-rows from
// shared A (broadcast). No syncs on the W path -> deep MLP.
template<int MT>
__global__ __launch_bounds__(256) void k_gemmW(
    const float* __restrict__ A, int lda,
    const float* __restrict__ W, int K,
    float* __restrict__ part, int N, int kchunk, int Mtot)
{
    const int P = MT / 16;                 // m-pairs per thread (4 or 2)
    __shared__ float As[64][MT + 4];
    int tid = threadIdx.x;
    int tx = tid & 31, ty = tid >> 5;
    int n0 = blockIdx.x * 128;
    int ks = blockIdx.z;
    int k0 = ks * kchunk;

    u64 acc[P][4];
    #pragma unroll
    for (int p = 0; p < P; p++)
        #pragma unroll
        for (int j = 0; j < 4; j++) acc[p][j] = 0ULL;

    const float* Wp0 = W + (size_t)(n0 + tx * 4 + 0) * K;
    const float* Wp1 = W + (size_t)(n0 + tx * 4 + 1) * K;
    const float* Wp2 = W + (size_t)(n0 + tx * 4 + 2) * K;
    const float* Wp3 = W + (size_t)(n0 + tx * 4 + 3) * K;

    for (int kc = 0; kc < kchunk; kc += 64) {
        __syncthreads();
        #pragma unroll
        for (int i = tid; i < MT * 16; i += 256) {
            int m = i >> 4, kq = i & 15;
            float4 v = *(const float4*)(A + (size_t)m * lda + k0 + kc + kq * 4);
            As[kq * 4 + 0][m] = v.x;
            As[kq * 4 + 1][m] = v.y;
            As[kq * 4 + 2][m] = v.z;
            As[kq * 4 + 3][m] = v.w;
        }
        __syncthreads();

        int kb = k0 + kc;
        float4 w0 = *(const float4*)(Wp0 + kb);
        float4 w1 = *(const float4*)(Wp1 + kb);
        float4 w2 = *(const float4*)(Wp2 + kb);
        float4 w3 = *(const float4*)(Wp3 + kb);

        #pragma unroll 4
        for (int kg = 0; kg < 64; kg += 4) {
            float4 n0v, n1v, n2v, n3v;
            if (kg < 60) {
                n0v = *(const float4*)(Wp0 + kb + kg + 4);
                n1v = *(const float4*)(Wp1 + kb + kg + 4);
                n2v = *(const float4*)(Wp2 + kb + kg + 4);
                n3v = *(const float4*)(Wp3 + kb + kg + 4);
            }
            #pragma unroll
            for (int c = 0; c < 4; c++) {
                u64 b0 = dup2(f4c(w0, c));
                u64 b1 = dup2(f4c(w1, c));
                u64 b2 = dup2(f4c(w2, c));
                u64 b3 = dup2(f4c(w3, c));
                const float* ar = &As[kg + c][ty * (MT / 8)];
                ulonglong2 a01 = *(const ulonglong2*)ar;
                ffma2(acc[0][0], a01.x, b0); ffma2(acc[0][1], a01.x, b1);
                ffma2(acc[0][2], a01.x, b2); ffma2(acc[0][3], a01.x, b3);
                ffma2(acc[1][0], a01.y, b0); ffma2(acc[1][1], a01.y, b1);
                ffma2(acc[1][2], a01.y, b2); ffma2(acc[1][3], a01.y, b3);
                if (P == 4) {
                    ulonglong2 a23 = *(const ulonglong2*)(ar + 4);
                    ffma2(acc[2][0], a23.x, b0); ffma2(acc[2][1], a23.x, b1);
                    ffma2(acc[2][2], a23.x, b2); ffma2(acc[2][3], a23.x, b3);
                    ffma2(acc[3][0], a23.y, b0); ffma2(acc[3][1], a23.y, b1);
                    ffma2(acc[3][2], a23.y, b2); ffma2(acc[3][3], a23.y, b3);
                }
            }
            if (kg < 60) { w0 = n0v; w1 = n1v; w2 = n2v; w3 = n3v; }
        }
    }

    float* Pp = part + ((size_t)ks * Mtot) * N + n0 + tx * 4;
    int mb = ty * (MT / 8);
    #pragma unroll
    for (int p = 0; p < P; p++) {
        float l0, h0, l1, h1, l2, h2, l3, h3;
        unpack2(acc[p][0], l0, h0);
        unpack2(acc[p][1], l1, h1);
        unpack2(acc[p][2], l2, h2);
        unpack2(acc[p][3], l3, h3);
        float4 lo = make_float4(l0, l1, l2, l3);
        float4 hi = make_float4(h0, h1, h2, h3);
        *(float4*)(Pp + (size_t)(mb + 2 * p + 0) * N) = lo;
        *(float4*)(Pp + (size_t)(mb + 2 * p + 1) * N) = hi;
    }
}

__device__ __forceinline__ float gelu_exact(float x)
{
    return 0.5f * x * (1.f + erff(x * 0.70710678118654752f));
}

// generic reduce (no LN)
__global__ void k_gemm_reduce(const float* __restrict__ part,
                              float* __restrict__ C, int ldc,
                              const float* __restrict__ bias,
                              const float* __restrict__ Res, int ldr,
                              int M, int N, int nsplit, int act)
{
    int n = blockIdx.x * 256 + threadIdx.x;
    int m = blockIdx.y;
    if (n >= N) return;
    float s = 0.f;
    for (int ks = 0; ks < nsplit; ks++) s += part[((size_t)ks * M + m) * N + n];
    s += bias[n];
    if (Res) s += Res[(size_t)m * ldr + n];
    if (act) s = gelu_exact(s);
    C[(size_t)m * ldc + n] = s;
}

// reduce + bias + residual -> C, then LayerNorm(C row) -> X. N==1024 fixed.
__global__ void k_reduce_ln(const float* __restrict__ part, int M, int nsplit,
                            const float* __restrict__ bias,
                            const float* __restrict__ Res, int ldr,
                            float* __restrict__ C, int ldc,
                            const float* __restrict__ lng, const float* __restrict__ lnb,
                            float* __restrict__ X, int ldx)
{
    __shared__ float2 red[256];
    int m = blockIdx.x, tid = threadIdx.x;
    float4 s4 = make_float4(0.f, 0.f, 0.f, 0.f);
    for (int ks = 0; ks < nsplit; ks++) {
        float4 v = ((const float4*)(part + ((size_t)ks * M + m) * 1024))[tid];
        s4.x += v.x; s4.y += v.y; s4.z += v.z; s4.w += v.w;
    }
    float4 bb = ((const float4*)bias)[tid];
    float4 rr = ((const float4*)(Res + (size_t)m * ldr))[tid];
    s4.x += bb.x + rr.x; s4.y += bb.y + rr.y;
    s4.z += bb.z + rr.z; s4.w += bb.w + rr.w;
    ((float4*)(C + (size_t)m * ldc))[tid] = s4;
    float s = s4.x + s4.y + s4.z + s4.w;
    float sq = s4.x * s4.x + s4.y * s4.y + s4.z * s4.z + s4.w * s4.w;
    red[tid] = make_float2(s, sq); __syncthreads();
    for (int st = 128; st > 0; st >>= 1) {
        if (tid < st) { red[tid].x += red[tid + st].x; red[tid].y += red[tid + st].y; }
        __syncthreads();
    }
    float mean = red[0].x * (1.f / 1024.f);
    float var  = red[0].y * (1.f / 1024.f) - mean * mean;
    float rstd = rsqrtf(var + 1e-5f);
    float4 gv = ((const float4*)lng)[tid];
    float4 bv = ((const float4*)lnb)[tid];
    float4 o;
    o.x = (s4.x - mean) * rstd * gv.x + bv.x;
    o.y = (s4.y - mean) * rstd * gv.y + bv.y;
    o.z = (s4.z - mean) * rstd * gv.z + bv.z;
    o.w = (s4.w - mean) * rstd * gv.w + bv.w;
    ((float4*)(X + (size_t)m * ldx))[tid] = o;
}

// ---------------- 2-token self-attention core --------------------------------
__global__ void k_selfattn(const float* __restrict__ t3, float* __restrict__ attn)
{
    int b = blockIdx.x, h = blockIdx.y, d = threadIdx.x;
    const float* r0 = t3 + (size_t)(b * 2 + 0) * 3072;
    const float* r1 = t3 + (size_t)(b * 2 + 1) * 3072;
    int j = h * 64 + d;
    float q0 = r0[j], k0 = r0[1024 + j], v0 = r0[2048 + j];
    float q1 = r1[j], k1 = r1[1024 + j], v1 = r1[2048 + j];
    __shared__ float sh[4][64];
    sh[0][d] = q0 * k0; sh[1][d] = q0 * k1; sh[2][d] = q1 * k0; sh[3][d] = q1 * k1;
    __syncthreads();
    for (int st = 32; st > 0; st >>= 1) {
        if (d < st) {
            #pragma unroll
            for (int i = 0; i < 4; i++) sh[i][d] += sh[i][d + st];
        }
        __syncthreads();
    }
    float s00 = sh[0][0] * 0.125f, s01 = sh[1][0] * 0.125f;
    float s10 = sh[2][0] * 0.125f, s11 = sh[3][0] * 0.125f;
    float m0 = fmaxf(s00, s01), m1 = fmaxf(s10, s11);
    float e00 = expf(s00 - m0), e01 = expf(s01 - m0);
    float e10 = expf(s10 - m1), e11 = expf(s11 - m1);
    float a00 = e00 / (e00 + e01), a01 = e01 / (e00 + e01);
    float a10 = e10 / (e10 + e11), a11 = e11 / (e10 + e11);
    attn[(size_t)(b * 2 + 0) * Dm + j] = a00 * v0 + a01 * v1;
    attn[(size_t)(b * 2 + 1) * Dm + j] = a10 * v0 + a11 * v1;
}

// ---------------- fold: u[b,h,:] = qp[b, h*64: ] @ wk_h ----------------------
__global__ void k_ufold(const float* __restrict__ qp, const float* __restrict__ wk,
                        float* __restrict__ u)
{
    int h = blockIdx.x;
    int e = blockIdx.y * 128 + threadIdx.x;
    __shared__ float qs[32][64];
    for (int i = threadIdx.x; i < 2048; i += 128)
        qs[i >> 6][i & 63] = qp[(size_t)(i >> 6) * Dm + h * 64 + (i & 63)];
    __syncthreads();
    float acc[32];
    #pragma unroll
    for (int b2 = 0; b2 < 32; b2++) acc[b2] = 0.f;
    for (int d = 0; d < 64; d++) {
        float w = wk[(size_t)(h * 64 + d) * Dm + e];
        #pragma unroll
        for (int b2 = 0; b2 < 32; b2++) acc[b2] += qs[b2][d] * w;
    }
    #pragma unroll
    for (int b2 = 0; b2 < 32; b2++) u[((size_t)b2 * Hh + h) * Dm + e] = acc[b2];
}

// ---------------- scores: s[b,h,n] = 0.125 * X[b,n,:] . u[b,h,:] -------------
__global__ __launch_bounds__(256) void k_scores(
    const float* __restrict__ X, const float* __restrict__ u,
    float* __restrict__ s, int Nt)
{
    extern __shared__ float ush[];   // 16*1024 floats = 64 KB
    int b = blockIdx.x, tid = threadIdx.x;
    const float4* usrc = (const float4*)(u + (size_t)b * Hh * Dm);
    #pragma unroll
    for (int i = 0; i < 16; i++) ((float4*)ush)[tid + i * 256] = usrc[tid + i * 256];
    __syncthreads();
    int w = tid >> 5, lane = tid & 31;
    for (int tl = 0; tl < 2; tl++) {
        int n0 = blockIdx.y * 64 + tl * 32 + w * 4;
        const ulonglong2* xp = (const ulonglong2*)(X + ((size_t)b * Nt + n0) * Dm);
        u64 acc[16][4];
        #pragma unroll
        for (int h = 0; h < 16; h++)
            #pragma unroll
            for (int t = 0; t < 4; t++) acc[h][t] = 0ULL;
        for (int i = 0; i < 8; i++) {
            ulonglong2 x0 = xp[0 * 256 + i * 32 + lane];
            ulonglong2 x1 = xp[1 * 256 + i * 32 + lane];
            ulonglong2 x2 = xp[2 * 256 + i * 32 + lane];
            ulonglong2 x3 = xp[3 * 256 + i * 32 + lane];
            #pragma unroll
            for (int h = 0; h < 16; h++) {
                ulonglong2 uv = *(const ulonglong2*)&ush[h * Dm + i * 128 + (lane << 2)];
                ffma2(acc[h][0], x0.x, uv.x); ffma2(acc[h][0], x0.y, uv.y);
                ffma2(acc[h][1], x1.x, uv.x); ffma2(acc[h][1], x1.y, uv.y);
                ffma2(acc[h][2], x2.x, uv.x); ffma2(acc[h][2], x2.y, uv.y);
                ffma2(acc[h][3], x3.x, uv.x); ffma2(acc[h][3], x3.y, uv.y);
            }
        }
        #pragma unroll
        for (int h = 0; h < 16; h++) {
            #pragma unroll
            for (int t = 0; t < 4; t++) {
                float v = sum2(acc[h][t]);
                #pragma unroll
                for (int off = 16; off; off >>= 1) v += __shfl_xor_sync(0xffffffffu, v, off);
                if (lane == 0) s[((size_t)b * Hh + h) * Nt + n0 + t] = v * 0.125f;
            }
        }
    }
}

// ---------------- row softmax over Nt ----------------------------------------
template <int CNT>
__global__ void k_softmax(float* __restrict__ s, int Nt)
{
    __shared__ float red[256];
    size_t base = (size_t)blockIdx.x * Nt;
    int tid = threadIdx.x;
    float v[CNT];
    float mx = -1e30f;
    #pragma unroll
    for (int i = 0; i < CNT; i++) { v[i] = s[base + i * 256 + tid]; mx = fmaxf(mx, v[i]); }
    red[tid] = mx; __syncthreads();
    for (int st = 128; st > 0; st >>= 1) {
        if (tid < st) red[tid] = fmaxf(red[tid], red[tid + st]);
        __syncthreads();
    }
    mx = red[0]; __syncthreads();
    float sum = 0.f;
    #pragma unroll
    for (int i = 0; i < CNT; i++) { v[i] = expf(v[i] - mx); sum += v[i]; }
    red[tid] = sum; __syncthreads();
    for (int st = 128; st > 0; st >>= 1) {
        if (tid < st) red[tid] += red[tid + st];
        __syncthreads();
    }
    float inv = 1.f / red[0];
    #pragma unroll
    for (int i = 0; i < CNT; i++) s[base + i * 256 + tid] = v[i] * inv;
}

// ---------------- wbar partials ----------------------------------------------
__global__ __launch_bounds__(256) void k_wbar_part(
    const float* __restrict__ X, const float* __restrict__ a,
    float* __restrict__ part, int Nt)
{
    __shared__ u64 ash2[256][17];
    int b = blockIdx.x, sp = blockIdx.y;
    int n0 = sp * 256;
    int tid = threadIdx.x;
    for (int idx = tid; idx < 4096; idx += 256) {
        int nn = idx & 255, h = idx >> 8;
        float av = a[((size_t)b * Hh + h) * Nt + n0 + nn];
        ash2[nn][h] = dup2(av);
    }
    __syncthreads();
    u64 acc[16][2];
    #pragma unroll
    for (int h = 0; h < 16; h++) { acc[h][0] = 0ULL; acc[h][1] = 0ULL; }
    const ulonglong2* xp = (const ulonglong2*)(X + ((size_t)b * Nt + n0) * Dm) + tid;
    for (int nn = 0; nn < 256; nn++) {
        ulonglong2 f = xp[(size_t)nn * 256];
        #pragma unroll
        for (int h = 0; h < 16; h++) {
            u64 aa = ash2[nn][h];
            ffma2(acc[h][0], aa, f.x);
            ffma2(acc[h][1], aa, f.y);
        }
    }
    ulonglong2* P = (ulonglong2*)(part + (((size_t)sp * Bsz + b) * Hh) * Dm);
    #pragma unroll
    for (int h = 0; h < 16; h++) {
        ulonglong2 v; v.x = acc[h][0]; v.y = acc[h][1];
        P[h * 256 + tid] = v;
    }
}

// ---------------- v-projection (fused split reduce) --------------------------
__global__ void k_vproj(const float* __restrict__ part, int NS,
                        const float* __restrict__ wv,
                        const float* __restrict__ bv, float* __restrict__ o)
{
    __shared__ float wsh[1024];
    int b = blockIdx.x, h = blockIdx.y, tid = threadIdx.x;
    float4 acc4 = make_float4(0.f, 0.f, 0.f, 0.f);
    for (int sp = 0; sp < NS; sp++) {
        float4 v = ((const float4*)(part + (((size_t)sp * Bsz + b) * Hh + h) * Dm))[tid];
        acc4.x += v.x; acc4.y += v.y; acc4.z += v.z; acc4.w += v.w;
    }
    ((float4*)wsh)[tid] = acc4;
    __syncthreads();
    int w = tid >> 5, lane = tid & 31;
    for (int dd = w; dd < 64; dd += 8) {
        int j = h * 64 + dd;
        const float4* wvp = (const float4*)(wv + (size_t)j * Dm);
        float acc = 0.f;
        #pragma unroll
        for (int i = 0; i < 8; i++) {
            float4 a = wvp[i * 32 + lane];
            float4 c = *(const float4*)&wsh[i * 128 + (lane << 2)];
            acc += a.x * c.x + a.y * c.y + a.z * c.z + a.w * c.w;
        }
        #pragma unroll
        for (int off = 16; off; off >>= 1) acc += __shfl_xor_sync(0xffffffffu, acc, off);
        if (lane == 0) o[(size_t)b * Dm + j] = acc + bv[j];
    }
}

extern "C" void kernel_launch(void* const* d_in, const int* in_sizes, int n_in,
                              void* d_out, int out_size)
{
    const float* frame = (const float*)d_in[0];
    const float* kvs   = (const float*)d_in[1];
    const float* maxi  = (const float*)d_in[2];
    const float* qbase = (const float*)d_in[3];
    const float* role  = (const float*)d_in[4];
    const float* timew = (const float*)d_in[5];
    const float* ln1g  = (const float*)d_in[6];
    const float* ln1b  = (const float*)d_in[7];
    const float* sa_in_w = (const float*)d_in[8];
    const float* sa_in_b = (const float*)d_in[9];
    const float* sa_out_w = (const float*)d_in[10];
    const float* sa_out_b = (const float*)d_in[11];
    const float* ln2g  = (const float*)d_in[12];
    const float* ln2b  = (const float*)d_in[13];
    const float* cg_in_w = (const float*)d_in[14];
    const float* cg_in_b = (const float*)d_in[15];
    const float* cg_out_w = (const float*)d_in[16];
    const float* cg_out_b = (const float*)d_in[17];
    const float* cs_in_w = (const float*)d_in[18];
    const float* cs_in_b = (const float*)d_in[19];
    const float* cs_out_w = (const float*)d_in[20];
    const float* cs_out_b = (const float*)d_in[21];
    const float* ln3g  = (const float*)d_in[22];
    const float* ln3b  = (const float*)d_in[23];
    const float* fw1   = (const float*)d_in[24];
    const float* fb1   = (const float*)d_in[25];
    const float* fw2   = (const float*)d_in[26];
    const float* fb2   = (const float*)d_in[27];
    const float* outg  = (const float*)d_in[28];
    const float* outb  = (const float*)d_in[29];
    const int*   fidx  = (const int*)d_in[30];
    float* outp = (float*)d_out;

    void* sp_;
    cudaGetSymbolAddress(&sp_, g_scratch);
    float* S = (float*)sp_;
    float* mpart = S;                   // 524288
    float* q     = mpart + 524288;      // 65536
    float* x     = q + 65536;           // 65536
    float* t3    = x + 65536;           // 196608
    float* attn  = t3 + 196608;         // 65536
    float* qpg   = attn + 65536;        // 32768
    float* qps   = qpg + 32768;         // 32768
    float* ug    = qps + 32768;         // 524288
    float* us    = ug + 524288;         // 524288
    float* sg    = us + 524288;         // 2097152
    float* ss    = sg + 2097152;        // 524288
    float* wpart = ss + 524288;         // 8388608
    float* og    = wpart + 8388608;     // 32768
    float* os    = og + 32768;          // 32768
    float* gpart = os + 32768;          // 3145728
    float* hh    = gpart + 3145728;     // 262144

    cudaFuncSetAttribute(k_scores, cudaFuncAttributeMaxDynamicSharedMemorySize, 65536);

    // init: mean + q assembly + first LN
    k_mean_part<<<dim3(32, 16), 256>>>(frame, mpart);
    k_qinit<<<32, 256>>>(mpart, maxi, qbase, role, timew, fidx, q);
    k_ln<<<64, 256>>>(q, ln1g, ln1b, x);

    for (int l = 0; l < 2; l++) {
        const float* siw = sa_in_w + (size_t)l * 3072 * Dm;
        const float* sib = sa_in_b + l * 3072;
        const float* sow = sa_out_w + (size_t)l * Dm * Dm;
        const float* sob = sa_out_b + l * Dm;
        const float* l2g = ln2g + l * Dm;   const float* l2b = ln2b + l * Dm;
        const float* giw = cg_in_w + (size_t)l * 3072 * Dm;
        const float* gib = cg_in_b + l * 3072;
        const float* gow = cg_out_w + (size_t)l * Dm * Dm;
        const float* gob = cg_out_b + l * Dm;
        const float* ciw = cs_in_w + (size_t)l * 3072 * Dm;
        const float* cib = cs_in_b + l * 3072;
        const float* cow = cs_out_w + (size_t)l * Dm * Dm;
        const float* cob = cs_out_b + l * Dm;
        const float* l3g = ln3g + l * Dm;   const float* l3b = ln3b + l * Dm;
        const float* w1 = fw1 + (size_t)l * 4096 * Dm;
        const float* b1 = fb1 + l * 4096;
        const float* w2 = fw2 + (size_t)l * Dm * 4096;
        const float* b2 = fb2 + l * Dm;
        const float* nlg = (l == 0) ? (ln1g + Dm) : outg;
        const float* nlb = (l == 0) ? (ln1b + Dm) : outb;
        float* nx = (l == 0) ? x : outp;

        // ---- self-attention (2 tokens): x is LN1(q) ----
        k_gemmW<64><<<dim3(24, 1, 8), 256>>>(x, 1024, siw, 1024, gpart, 3072, 128, 64);
        k_gemm_reduce<<<dim3(12, 64), 256>>>(gpart, t3, 3072, sib, nullptr, 0, 64, 3072, 8, 0);
        k_selfattn<<<dim3(32, 16), 64>>>(t3, attn);
        k_gemmW<64><<<dim3(8, 1, 16), 256>>>(attn, 1024, sow, 1024, gpart, 1024, 64, 64);
        k_reduce_ln<<<64, 256>>>(gpart, 64, 16, sob, q, 1024, q, 1024, l2g, l2b, x, 1024);

        // ---- cross-attention (folded K/V) ----
        k_gemmW<32><<<dim3(8, 1, 16), 256>>>(x, 2048, giw, 1024, gpart, 1024, 64, 32);
        k_gemm_reduce<<<dim3(4, 32), 256>>>(gpart, qpg, 1024, gib, nullptr, 0, 32, 1024, 16, 0);
        k_gemmW<32><<<dim3(8, 1, 16), 256>>>(x + 1024, 2048, ciw, 1024, gpart, 1024, 64, 32);
        k_gemm_reduce<<<dim3(4, 32), 256>>>(gpart, qps, 1024, cib, nullptr, 0, 32, 1024, 16, 0);
        k_ufold<<<dim3(16, 8), 128>>>(qpg, giw + 1024 * 1024, ug);
        k_ufold<<<dim3(16, 8), 128>>>(qps, ciw + 1024 * 1024, us);
        k_scores<<<dim3(32, 64), 256, 65536>>>(frame, ug, sg, Nf);
        k_scores<<<dim3(32, 16), 256, 65536>>>(kvs, us, ss, Kv);
        k_softmax<16><<<512, 256>>>(sg, Nf);
        k_softmax<4><<<512, 256>>>(ss, Kv);
        k_wbar_part<<<dim3(32, 16), 256>>>(frame, sg, wpart, Nf);
        k_vproj<<<dim3(32, 16), 256>>>(wpart, 16, giw + 2 * 1024 * 1024, gib + 2048, og);
        k_wbar_part<<<dim3(32, 4), 256>>>(kvs, ss, wpart, Kv);
        k_vproj<<<dim3(32, 16), 256>>>(wpart, 4, ciw + 2 * 1024 * 1024, cib + 2048, os);
        k_gemmW<32><<<dim3(8, 1, 16), 256>>>(og, 1024, gow, 1024, gpart, 1024, 64, 32);
        k_reduce_ln<<<32, 256>>>(gpart, 32, 16, gob, q, 2048, q, 2048, l3g, l3b, x, 2048);
        k_gemmW<32><<<dim3(8, 1, 16), 256>>>(os, 1024, cow, 1024, gpart, 1024, 64, 32);
        k_reduce_ln<<<32, 256>>>(gpart, 32, 16, cob, q + 1024, 2048, q + 1024, 2048,
                                 l3g, l3b, x + 1024, 2048);

        // ---- FFN: x is LN3(q) ----
        k_gemmW<64><<<dim3(32, 1, 8), 256>>>(x, 1024, w1, 1024, gpart, 4096, 128, 64);
        k_gemm_reduce<<<dim3(16, 64), 256>>>(gpart, hh, 4096, b1, nullptr, 0, 64, 4096, 8, 1);
        k_gemmW<64><<<dim3(8, 1, 32), 256>>>(hh, 4096, w2, 4096, gpart, 1024, 128, 64);
        k_reduce_ln<<<64, 256>>>(gpart, 64, 32, b2, q, 1024, q, 1024, nlg, nlb, nx, 1024);
    }
}